// round 14
// baseline (speedup 1.0000x reference)
#include <cuda_runtime.h>
#include <cuda_bf16.h>
#include <cstdint>

#define B_ 16
#define N_ 16384
#define CH 64
#define S_ 64
#define K_ 64
#define OUT1 (B_*128*N_)
#define OUT2 (OUT1 + B_*CH*S_)

typedef unsigned long long u64;

__device__ float g_feaT[(size_t)B_ * N_ * CH];
__device__ float g_xnorm[B_ * N_];
__device__ float g_fploc[B_ * S_ * 3];
__device__ float g_fpfea[B_ * S_ * CH];
__device__ float g_nodeloc[B_ * S_ * 3];
__device__ float g_M[CH * CH];
__device__ float g_mu[CH];
__device__ float g_scale[CH];
__device__ float g_shift[CH];
__device__ float g_wT[CH * CH];

__device__ __forceinline__ float sq3_rn(float x, float y, float z) {
    return __fadd_rn(__fadd_rn(__fmul_rn(x, x), __fmul_rn(y, y)), __fmul_rn(z, z));
}
__device__ __forceinline__ u64 pk2(float lo, float hi) {
    u64 r; asm("mov.b64 %0,{%1,%2};" : "=l"(r) : "f"(lo), "f"(hi)); return r;
}
__device__ __forceinline__ void upk2(u64 v, float& lo, float& hi) {
    asm("mov.b64 {%0,%1},%2;" : "=f"(lo), "=f"(hi) : "l"(v));
}
__device__ __forceinline__ u64 add2(u64 a, u64 b) {
    u64 r; asm("add.rn.f32x2 %0,%1,%2;" : "=l"(r) : "l"(a), "l"(b)); return r;
}
__device__ __forceinline__ u64 mul2(u64 a, u64 b) {
    u64 r; asm("mul.rn.f32x2 %0,%1,%2;" : "=l"(r) : "l"(a), "l"(b)); return r;
}
__device__ __forceinline__ u64 fma2(u64 a, u64 b, u64 c) {
    u64 r; asm("fma.rn.f32x2 %0,%1,%2,%3;" : "=l"(r) : "l"(a), "l"(b), "l"(c)); return r;
}

// ---------- xnorm (+ zero of M/mu in block 0) ----------
__global__ __launch_bounds__(256) void k_xnorm(const float* __restrict__ loc) {
    int idx = blockIdx.x * 256 + threadIdx.x;
    int b = idx >> 14, n = idx & (N_ - 1);
    const float* lb = loc + (size_t)b * 3 * N_;
    g_xnorm[idx] = sq3_rn(lb[n], lb[N_ + n], lb[2 * N_ + n]);
    if (blockIdx.x == 0) {
        int t = threadIdx.x;
        for (int j = t; j < CH * CH; j += 256) g_M[j] = 0.f;
        if (t < CH) g_mu[t] = 0.f;
    }
}

// ---------- transpose fea -> [b][n][c] ----------
__global__ __launch_bounds__(256) void k_transpose(const float* __restrict__ fea) {
    __shared__ float t[32][33];
    int b = blockIdx.z, c0 = blockIdx.y * 32, n0 = blockIdx.x * 32;
    int tx = threadIdx.x, ty = threadIdx.y;
    const float* src = fea + ((size_t)b * CH + c0) * N_ + n0;
#pragma unroll
    for (int k = 0; k < 4; k++) t[ty + k * 8][tx] = src[(size_t)(ty + k * 8) * N_ + tx];
    __syncthreads();
    float* dst = g_feaT + ((size_t)b * N_ + n0) * CH + c0;
#pragma unroll
    for (int k = 0; k < 4; k++) dst[(size_t)(ty + k * 8) * CH + tx] = t[tx][ty + k * 8];
}

// ---------- fused: blocks 0-15 FPS, blocks 16-271 second moments ----------
__global__ __launch_bounds__(512) void k_fps_mom(const float* __restrict__ loc) {
    __shared__ __align__(16) float tile[128 * CH];   // moments tile (32KB), MUST be 16B-aligned
    __shared__ u64 s_red[16];
    __shared__ int s_far;
    __shared__ int s_fidx[S_];
    int tid = threadIdx.x;

    if (blockIdx.x < 16) {
        // ===== FPS (identical to round 12) =====
        int b = blockIdx.x;
        const float* lx = loc + (size_t)b * 3 * N_;
        const float* ly = lx + N_;
        const float* lz = ly + N_;
        u64 pyp[16], pzp[16];
        float dist[32];
#pragma unroll
        for (int i = 0; i < 16; i++) {
            int n = 2 * tid + i * 1024;
            pyp[i] = *(const u64*)(ly + n);
            pzp[i] = *(const u64*)(lz + n);
            dist[2 * i] = 1e10f; dist[2 * i + 1] = 1e10f;
        }
        int far = 0;
        for (int s = 0; s < S_; s++) {
            if (tid == 0) s_fidx[s] = far;
            float cx = lx[far], cy = ly[far], cz = lz[far];
            u64 ncx = pk2(-cx, -cx), ncy = pk2(-cy, -cy), ncz = pk2(-cz, -cz);
            float bestd = -1.f; int bestn = 0;
#pragma unroll
            for (int i = 0; i < 16; i++) {
                int n = 2 * tid + i * 1024;
                u64 pxp = *(const u64*)(lx + n);
                u64 dx = add2(pxp, ncx), dy = add2(pyp[i], ncy), dz = add2(pzp[i], ncz);
                u64 sum = add2(add2(mul2(dx, dx), mul2(dy, dy)), mul2(dz, dz));
                float d0, d1; upk2(sum, d0, d1);
                float m0 = fminf(dist[2 * i], d0);     dist[2 * i] = m0;
                float m1 = fminf(dist[2 * i + 1], d1); dist[2 * i + 1] = m1;
                if (m0 > bestd) { bestd = m0; bestn = n; }
                if (m1 > bestd) { bestd = m1; bestn = n + 1; }
            }
            u64 key = ((u64)__float_as_uint(bestd) << 32) | (unsigned)(0xFFFFFFFFu - (unsigned)bestn);
#pragma unroll
            for (int off = 16; off; off >>= 1) {
                u64 o = __shfl_down_sync(0xffffffffu, key, off);
                if (o > key) key = o;
            }
            if ((tid & 31) == 0) s_red[tid >> 5] = key;
            __syncthreads();
            if (tid < 32) {
                u64 v = (tid < 16) ? s_red[tid] : 0ull;
#pragma unroll
                for (int off = 8; off; off >>= 1) {
                    u64 o = __shfl_down_sync(0xffffffffu, v, off);
                    if (o > v) v = o;
                }
                if (tid == 0) s_far = (int)(0xFFFFFFFFu - (unsigned)(v & 0xFFFFFFFFull));
            }
            __syncthreads();
            far = s_far;
        }
        if (tid < S_) {
            int n = s_fidx[tid];
            g_fploc[(b * S_ + tid) * 3 + 0] = lx[n];
            g_fploc[(b * S_ + tid) * 3 + 1] = ly[n];
            g_fploc[(b * S_ + tid) * 3 + 2] = lz[n];
        }
        __syncthreads();
        for (int j = tid; j < S_ * CH; j += 512) {
            int s = j >> 6, c = j & 63;
            g_fpfea[b * S_ * CH + j] = g_feaT[((size_t)(b * N_ + s_fidx[s])) * CH + c];
        }
    } else {
        // ===== second moments, 512-thread 2x4 tiling (same summation order) =====
        int blk = blockIdx.x - 16;
        int b = blk >> 4;
        int p0 = (blk & 15) * 1024;
        int r0 = (tid >> 4) << 1;        // 0..62 step 2
        int c0 = (tid & 15) << 2;        // 0..60 step 4
        float acc[8];
#pragma unroll
        for (int i = 0; i < 8; i++) acc[i] = 0.f;
        float mu = 0.f;
        for (int t = 0; t < 8; t++) {
            const float4* src = (const float4*)(g_feaT + ((size_t)(b * N_ + p0 + t * 128)) * CH);
            float4* dst4 = (float4*)tile;
            for (int j = tid; j < 128 * CH / 4; j += 512) dst4[j] = src[j];
            __syncthreads();
            for (int p = 0; p < 128; p++) {
                float2 av = *(const float2*)&tile[p * CH + r0];
                float4 bv = *(const float4*)&tile[p * CH + c0];
                acc[0] = fmaf(av.x, bv.x, acc[0]); acc[1] = fmaf(av.x, bv.y, acc[1]);
                acc[2] = fmaf(av.x, bv.z, acc[2]); acc[3] = fmaf(av.x, bv.w, acc[3]);
                acc[4] = fmaf(av.y, bv.x, acc[4]); acc[5] = fmaf(av.y, bv.y, acc[5]);
                acc[6] = fmaf(av.y, bv.z, acc[6]); acc[7] = fmaf(av.y, bv.w, acc[7]);
            }
            if (tid < CH)
                for (int p = 0; p < 128; p++) mu += tile[p * CH + tid];
            __syncthreads();
        }
#pragma unroll
        for (int i = 0; i < 2; i++)
#pragma unroll
            for (int j = 0; j < 4; j++)
                atomicAdd(&g_M[(r0 + i) * CH + (c0 + j)], acc[i * 4 + j]);
        if (tid < CH) atomicAdd(&g_mu[tid], mu);
    }
}

// ---------- ball query (256 pts/iter) + node_offset ----------
__global__ __launch_bounds__(128) void k_ball(const float* __restrict__ loc,
                                              const float* __restrict__ w_off,
                                              float* __restrict__ out) {
    __shared__ int   s_idx[K_];
    __shared__ float s_fpf[CH];
    __shared__ float s_w[3 * CH];
    __shared__ float s_p[3];
    __shared__ int   s_cnt;
    __shared__ float s_part[2][3];
    int s = blockIdx.x, b = blockIdx.y, tid = threadIdx.x;
    int lane = tid & 31;
    for (int j = tid; j < 3 * CH; j += 128) s_w[j] = w_off[j];
    if (tid < CH) s_fpf[tid] = g_fpfea[(b * S_ + s) * CH + tid];
    if (tid < 3) s_p[tid] = g_fploc[(b * S_ + s) * 3 + tid];
    if (tid == 0) s_cnt = 0;
    __syncthreads();
    float px = s_p[0], py = s_p[1], pz = s_p[2];
    float pp = sq3_rn(px, py, pz);
    if (tid < 32) {
        const float R2 = 0.3f * 0.3f;
        const float* lx = loc + (size_t)b * 3 * N_;
        const float* ly = lx + N_;
        const float* lz = ly + N_;
        const float* xn = g_xnorm + b * N_;
        int cnt = 0;
        for (int base = 0; base < N_ && cnt < K_; base += 256) {
            int n0 = base + 8 * lane;
            float4 xv0 = *(const float4*)(lx + n0);
            float4 xv1 = *(const float4*)(lx + n0 + 4);
            float4 yv0 = *(const float4*)(ly + n0);
            float4 yv1 = *(const float4*)(ly + n0 + 4);
            float4 zv0 = *(const float4*)(lz + n0);
            float4 zv1 = *(const float4*)(lz + n0 + 4);
            float4 nv0 = *(const float4*)(xn + n0);
            float4 nv1 = *(const float4*)(xn + n0 + 4);
            unsigned inm = 0;
            {
                float xa[8] = {xv0.x, xv0.y, xv0.z, xv0.w, xv1.x, xv1.y, xv1.z, xv1.w};
                float ya[8] = {yv0.x, yv0.y, yv0.z, yv0.w, yv1.x, yv1.y, yv1.z, yv1.w};
                float za[8] = {zv0.x, zv0.y, zv0.z, zv0.w, zv1.x, zv1.y, zv1.z, zv1.w};
                float na[8] = {nv0.x, nv0.y, nv0.z, nv0.w, nv1.x, nv1.y, nv1.z, nv1.w};
#pragma unroll
                for (int j = 0; j < 8; j++) {
                    float dot = fmaf(pz, za[j], fmaf(py, ya[j], __fmul_rn(px, xa[j])));
                    bool in = !(__fadd_rn(__fadd_rn(__fmul_rn(-2.0f, dot), pp), na[j]) > R2);
                    inm |= ((unsigned)in) << j;
                }
            }
            int myc = __popc(inm);
            int scan = myc;
#pragma unroll
            for (int off = 1; off < 32; off <<= 1) {
                int t = __shfl_up_sync(0xffffffffu, scan, off);
                if (lane >= off) scan += t;
            }
            int total = __shfl_sync(0xffffffffu, scan, 31);
            int p = cnt + scan - myc;
#pragma unroll
            for (int j = 0; j < 8; j++) {
                if (inm & (1u << j)) { if (p < K_) s_idx[p] = n0 + j; p++; }
            }
            cnt += total;
        }
        if (tid == 0) s_cnt = cnt < K_ ? cnt : K_;
    }
    __syncthreads();
    int cnt = s_cnt;
    if (tid >= cnt && tid < K_) s_idx[tid] = s_idx[0];
    __syncthreads();
    float c0 = 0.f, c1 = 0.f, c2 = 0.f;
    if (tid < K_) {
        int n = s_idx[tid];
        const float4* fr = (const float4*)(g_feaT + ((size_t)(b * N_ + n)) * CH);
        float a0 = 0.f, a1 = 0.f, a2 = 0.f;
#pragma unroll
        for (int j = 0; j < 16; j++) {
            float4 f = fr[j];
            float g0 = f.x - s_fpf[4 * j + 0];
            float g1 = f.y - s_fpf[4 * j + 1];
            float g2 = f.z - s_fpf[4 * j + 2];
            float g3 = f.w - s_fpf[4 * j + 3];
            a0 = fmaf(s_w[4 * j + 0], g0, a0); a0 = fmaf(s_w[4 * j + 1], g1, a0);
            a0 = fmaf(s_w[4 * j + 2], g2, a0); a0 = fmaf(s_w[4 * j + 3], g3, a0);
            a1 = fmaf(s_w[CH + 4 * j + 0], g0, a1); a1 = fmaf(s_w[CH + 4 * j + 1], g1, a1);
            a1 = fmaf(s_w[CH + 4 * j + 2], g2, a1); a1 = fmaf(s_w[CH + 4 * j + 3], g3, a1);
            a2 = fmaf(s_w[2 * CH + 4 * j + 0], g0, a2); a2 = fmaf(s_w[2 * CH + 4 * j + 1], g1, a2);
            a2 = fmaf(s_w[2 * CH + 4 * j + 2], g2, a2); a2 = fmaf(s_w[2 * CH + 4 * j + 3], g3, a2);
        }
        float t0 = tanhf(a0), t1 = tanhf(a1), t2 = tanhf(a2);
        const float* lp = loc + (size_t)b * 3 * N_;
        c0 = t0 * (lp[n] - px);
        c1 = t1 * (lp[N_ + n] - py);
        c2 = t2 * (lp[2 * N_ + n] - pz);
    }
#pragma unroll
    for (int off = 16; off; off >>= 1) {
        c0 += __shfl_down_sync(0xffffffffu, c0, off);
        c1 += __shfl_down_sync(0xffffffffu, c1, off);
        c2 += __shfl_down_sync(0xffffffffu, c2, off);
    }
    if (tid < K_ && (tid & 31) == 0) {
        s_part[tid >> 5][0] = c0; s_part[tid >> 5][1] = c1; s_part[tid >> 5][2] = c2;
    }
    __syncthreads();
    if (tid == 0) {
        float o0 = (s_part[0][0] + s_part[1][0]) * 0.015625f;
        float o1 = (s_part[0][1] + s_part[1][1]) * 0.015625f;
        float o2 = (s_part[0][2] + s_part[1][2]) * 0.015625f;
        out[OUT2 + b * 3 * S_ + 0 * S_ + s] = o0;
        out[OUT2 + b * 3 * S_ + 1 * S_ + s] = o1;
        out[OUT2 + b * 3 * S_ + 2 * S_ + s] = o2;
        g_nodeloc[(b * S_ + s) * 3 + 0] = px + o0;
        g_nodeloc[(b * S_ + s) * 3 + 1] = py + o1;
        g_nodeloc[(b * S_ + s) * 3 + 2] = pz + o2;
    }
}

// ---------- BN constants + wT ----------
__global__ __launch_bounds__(256) void k_bn(const float* __restrict__ w,
                                            const float* __restrict__ b_res,
                                            const float* __restrict__ g_res,
                                            const float* __restrict__ be_res) {
    __shared__ float sM[CH * CH];
    __shared__ float sw[CH * CH];
    __shared__ float smu[CH];
    int tid = threadIdx.x;
    for (int j = tid; j < CH * CH; j += 256) { sM[j] = g_M[j]; sw[j] = w[j]; }
    if (tid < CH) smu[tid] = g_mu[tid];
    __syncthreads();
    const float invNp = 1.0f / (float)((size_t)B_ * N_);
    if (tid < CH) {
        int o = tid;
        float m1 = 0.f, ey2 = 0.f;
        for (int c = 0; c < CH; c++) {
            float wc = sw[o * CH + c];
            m1 = fmaf(wc, smu[c], m1);
            float r = 0.f;
            for (int c2 = 0; c2 < CH; c2++) r = fmaf(sw[o * CH + c2], sM[c * CH + c2], r);
            ey2 = fmaf(wc, r, ey2);
        }
        m1 *= invNp; ey2 *= invNp;
        float var = ey2 - m1 * m1;
        float meanY = m1 + b_res[o];
        float sc = rsqrtf(var + 1e-5f) * g_res[o];
        g_scale[o] = sc;
        g_shift[o] = fmaf(b_res[o] - meanY, sc, be_res[o]);
    }
    for (int j = tid; j < CH * CH; j += 256) {
        int c = j >> 6, o = j & 63;
        g_wT[c * CH + o] = sw[o * CH + c];
    }
}

// ---------- kNN-64 + fused GEMM/kmax/BN/relu ----------
__global__ __launch_bounds__(256) void k_knn(const float* __restrict__ loc,
                                             float* __restrict__ out) {
    extern __shared__ float s_dyn[];               // 64KB
    unsigned* s_keys = (unsigned*)s_dyn;
    __shared__ unsigned short s_h[8][16];
    __shared__ unsigned sPref;
    __shared__ int sWant, sC1, sCT;
    __shared__ int s_out[K_];
    __shared__ int s_tie[128];
    __shared__ float s_red[4 * CH];
    int s = blockIdx.x, b = blockIdx.y, tid = threadIdx.x;
    int lane = tid & 31, wid = tid >> 5;
    float qx = g_nodeloc[(b * S_ + s) * 3 + 0];
    float qy = g_nodeloc[(b * S_ + s) * 3 + 1];
    float qz = g_nodeloc[(b * S_ + s) * 3 + 2];
    float qq = sq3_rn(qx, qy, qz);
    const float* lx = loc + (size_t)b * 3 * N_;
    const float* ly = lx + N_;
    const float* lz = ly + N_;
    const float* xn = g_xnorm + b * N_;
    u64 qx2 = pk2(qx, qx), qy2 = pk2(qy, qy), qz2 = pk2(qz, qz);
    u64 qq2 = pk2(qq, qq), m2 = pk2(-2.0f, -2.0f);
    for (int i = 0; i < 32; i++) {
        int n = 2 * (tid + i * 256);
        u64 lxp = *(const u64*)(lx + n);
        u64 lyp = *(const u64*)(ly + n);
        u64 lzp = *(const u64*)(lz + n);
        u64 dot = fma2(qz2, lzp, fma2(qy2, lyp, mul2(qx2, lxp)));
        u64 d = add2(add2(mul2(m2, dot), qq2), *(const u64*)(xn + n));
        float d0, d1; upk2(d, d0, d1);
        unsigned u0 = __float_as_uint(d0);
        u0 = (u0 & 0x80000000u) ? ~u0 : (u0 | 0x80000000u);
        unsigned u1 = __float_as_uint(d1);
        u1 = (u1 & 0x80000000u) ? ~u1 : (u1 | 0x80000000u);
        *(u64*)(s_keys + n) = ((u64)u1 << 32) | u0;
    }
    if (tid == 0) { sPref = 0u; sWant = K_; sC1 = 0; sCT = 0; }
    __syncthreads();
    for (int p = 7; p >= 0; p--) {
        int sh = p * 4;
        unsigned himask = (p == 7) ? 0u : (0xFFFFFFFFu << (sh + 4));
        unsigned pref = sPref;
        u64 clo = 0ull, chi = 0ull;
        for (int i = 0; i < 64; i++) {
            unsigned k = s_keys[tid + i * 256];
            if ((k & himask) == pref) {
                unsigned d4 = (k >> sh) & 15u;
                u64 inc = 1ull << ((d4 & 7u) * 8u);
                if (d4 < 8u) clo += inc; else chi += inc;
            }
        }
        const u64 M0 = 0x00FF00FF00FF00FFull;
        u64 e0 = clo & M0, e1 = (clo >> 8) & M0;
        u64 e2 = chi & M0, e3 = (chi >> 8) & M0;
#pragma unroll
        for (int off = 16; off; off >>= 1) {
            e0 += __shfl_down_sync(0xffffffffu, e0, off);
            e1 += __shfl_down_sync(0xffffffffu, e1, off);
            e2 += __shfl_down_sync(0xffffffffu, e2, off);
            e3 += __shfl_down_sync(0xffffffffu, e3, off);
        }
        if (lane == 0) {
#pragma unroll
            for (int j = 0; j < 4; j++) {
                s_h[wid][2 * j]     = (unsigned short)((e0 >> (16 * j)) & 0xFFFFull);
                s_h[wid][2 * j + 1] = (unsigned short)((e1 >> (16 * j)) & 0xFFFFull);
                s_h[wid][8 + 2 * j] = (unsigned short)((e2 >> (16 * j)) & 0xFFFFull);
                s_h[wid][9 + 2 * j] = (unsigned short)((e3 >> (16 * j)) & 0xFFFFull);
            }
        }
        __syncthreads();
        if (tid < 16) {
            int c = 0;
#pragma unroll
            for (int w = 0; w < 8; w++) c += (int)s_h[w][tid];
            int inc = c;
#pragma unroll
            for (int off = 1; off < 16; off <<= 1) {
                int t = __shfl_up_sync(0x0000FFFFu, inc, off);
                if (lane >= off) inc += t;
            }
            int excl = inc - c;
            int want = sWant;
            if (excl < want && want <= inc) {
                sPref = pref | ((unsigned)tid << sh);
                sWant = want - excl;
            }
        }
        __syncthreads();
    }
    unsigned pivot = sPref;
    int need = sWant;
    for (int i = 0; i < 64; i++) {
        int n = tid + i * 256;
        unsigned k = s_keys[n];
        if (k < pivot) { int p0 = atomicAdd(&sC1, 1); s_out[p0] = n; }
        else if (k == pivot) { int p0 = atomicAdd(&sCT, 1); if (p0 < 128) s_tie[p0] = n; }
    }
    __syncthreads();
    if (tid == 0) {
        int c1 = sC1, nt = sCT; if (nt > 128) nt = 128;
        for (int j = 0; j < need; j++) {
            int bi = -1, bv = 0x7fffffff;
            for (int t = 0; t < nt; t++) { int v2 = s_tie[t]; if (v2 >= 0 && v2 < bv) { bv = v2; bi = t; } }
            s_out[c1 + j] = bv;
            if (bi >= 0) s_tie[bi] = -1;
        }
    }
    __syncthreads();
    float* xg = s_dyn;                 // [64][64]
    float* sWT = s_dyn + 4096;         // [c][o]
    for (int j = tid; j < 1024; j += 256) {
        int r = j >> 4, c4 = j & 15;
        float4 f = ((const float4*)(g_feaT + ((size_t)(b * N_ + s_out[r])) * CH))[c4];
        ((float4*)xg)[j] = f;
        ((float4*)sWT)[j] = ((const float4*)g_wT)[j];
    }
    __syncthreads();
    int o = tid & 63, kseg = tid >> 6;
    u64 wp[32];
#pragma unroll
    for (int c = 0; c < 32; c++) wp[c] = pk2(sWT[(2 * c) * 64 + o], sWT[(2 * c + 1) * 64 + o]);
    float mx = -3.4e38f;
    for (int k = kseg * 16; k < kseg * 16 + 16; k++) {
        const ulonglong2* xr = (const ulonglong2*)(xg + (k << 6));
        u64 acc2 = 0ull;
#pragma unroll
        for (int c4 = 0; c4 < 16; c4++) {
            ulonglong2 f = xr[c4];
            acc2 = fma2(wp[2 * c4], f.x, acc2);
            acc2 = fma2(wp[2 * c4 + 1], f.y, acc2);
        }
        float alo, ahi; upk2(acc2, alo, ahi);
        mx = fmaxf(mx, alo + ahi);
    }
    s_red[kseg * 64 + o] = mx;
    __syncthreads();
    if (tid < 64) {
        float m = fmaxf(fmaxf(s_red[tid], s_red[64 + tid]), fmaxf(s_red[128 + tid], s_red[192 + tid]));
        float val = fmaxf(fmaf(m, g_scale[tid], g_shift[tid]), 0.f);
        out[OUT1 + (b * CH + tid) * S_ + s] = val;
    }
}

// ---------- upsample ----------
__global__ __launch_bounds__(256) void k_up(const float* __restrict__ loc,
                                            const float* __restrict__ fea,
                                            float* __restrict__ out) {
    __shared__ float nx[64], ny[64], nz[64], nn[64];
    __shared__ float nf[64 * 65];
    int b = blockIdx.y, n0 = blockIdx.x * 256, tid = threadIdx.x;
    if (tid < 64) {
        float x = g_nodeloc[(b * S_ + tid) * 3 + 0];
        float y = g_nodeloc[(b * S_ + tid) * 3 + 1];
        float z = g_nodeloc[(b * S_ + tid) * 3 + 2];
        nx[tid] = x; ny[tid] = y; nz[tid] = z; nn[tid] = sq3_rn(x, y, z);
    }
    for (int j = tid; j < 64 * 64; j += 256) {
        int c = j >> 6, s2 = j & 63;
        nf[c * 65 + s2] = out[OUT1 + (b * CH + c) * S_ + s2];
    }
    __syncthreads();
    int n = n0 + tid;
    const float* lp = loc + (size_t)b * 3 * N_;
    float px = lp[n], py = lp[N_ + n], pz = lp[2 * N_ + n];
    float pn = g_xnorm[b * N_ + n];
    float d0 = 3.4e38f, d1 = 3.4e38f, d2 = 3.4e38f;
    int i0 = 0, i1 = 0, i2 = 0;
    for (int s2 = 0; s2 < 64; s2++) {
        float dot = fmaf(pz, nz[s2], fmaf(py, ny[s2], __fmul_rn(px, nx[s2])));
        float d = __fadd_rn(__fadd_rn(__fmul_rn(-2.0f, dot), pn), nn[s2]);
        if (d < d0)      { d2 = d1; i2 = i1; d1 = d0; i1 = i0; d0 = d; i0 = s2; }
        else if (d < d1) { d2 = d1; i2 = i1; d1 = d; i1 = s2; }
        else if (d < d2) { d2 = d; i2 = s2; }
    }
    float w0 = 1.0f / fmaxf(d0, 1e-10f);
    float w1 = 1.0f / fmaxf(d1, 1e-10f);
    float w2 = 1.0f / fmaxf(d2, 1e-10f);
    float ws = __fadd_rn(__fadd_rn(w0, w1), w2);
    w0 /= ws; w1 /= ws; w2 /= ws;
    const float* fb = fea + (size_t)b * CH * N_ + n;
    float* ob = out + (size_t)b * 128 * N_ + n;
#pragma unroll 8
    for (int c = 0; c < 64; c++) ob[(size_t)c * N_] = fb[(size_t)c * N_];
#pragma unroll 8
    for (int c = 0; c < 64; c++) {
        float v = fmaf(nf[c * 65 + i2], w2, fmaf(nf[c * 65 + i1], w1, __fmul_rn(nf[c * 65 + i0], w0)));
        ob[(size_t)(64 + c) * N_] = v;
    }
}

extern "C" void kernel_launch(void* const* d_in, const int* in_sizes, int n_in,
                              void* d_out, int out_size) {
    const float* fea    = (const float*)d_in[0];
    const float* loc    = (const float*)d_in[1];
    const float* w_res  = (const float*)d_in[2];
    const float* b_res  = (const float*)d_in[3];
    const float* g_res  = (const float*)d_in[4];
    const float* be_res = (const float*)d_in[5];
    const float* w_off  = (const float*)d_in[6];
    float* out = (float*)d_out;

    cudaFuncSetAttribute(k_knn, cudaFuncAttributeMaxDynamicSharedMemorySize, 65536);

    k_xnorm<<<(B_ * N_) / 256, 256>>>(loc);
    k_transpose<<<dim3(N_ / 32, CH / 32, B_), dim3(32, 8)>>>(fea);
    k_fps_mom<<<16 + 256, 512>>>(loc);
    k_ball<<<dim3(S_, B_), 128>>>(loc, w_off, out);
    k_bn<<<1, 256>>>(w_res, b_res, g_res, be_res);
    k_knn<<<dim3(S_, B_), 256, 65536>>>(loc, out);
    k_up<<<dim3(N_ / 256, B_), 256>>>(loc, fea, out);
}

// round 15
// speedup vs baseline: 1.3311x; 1.3311x over previous
#include <cuda_runtime.h>
#include <cuda_bf16.h>
#include <cstdint>

#define B_ 16
#define N_ 16384
#define CH 64
#define S_ 64
#define K_ 64
#define OUT1 (B_*128*N_)
#define OUT2 (OUT1 + B_*CH*S_)

typedef unsigned long long u64;

__device__ float g_feaT[(size_t)B_ * N_ * CH];
__device__ float g_xnorm[B_ * N_];
__device__ float g_fploc[B_ * S_ * 3];
__device__ float g_fpfea[B_ * S_ * CH];
__device__ float g_nodeloc[B_ * S_ * 3];
__device__ float g_M[CH * CH];
__device__ float g_mu[CH];
__device__ float g_scale[CH];
__device__ float g_shift[CH];
__device__ float g_wT[CH * CH];

__device__ __forceinline__ float sq3_rn(float x, float y, float z) {
    return __fadd_rn(__fadd_rn(__fmul_rn(x, x), __fmul_rn(y, y)), __fmul_rn(z, z));
}
__device__ __forceinline__ u64 pk2(float lo, float hi) {
    u64 r; asm("mov.b64 %0,{%1,%2};" : "=l"(r) : "f"(lo), "f"(hi)); return r;
}
__device__ __forceinline__ void upk2(u64 v, float& lo, float& hi) {
    asm("mov.b64 {%0,%1},%2;" : "=f"(lo), "=f"(hi) : "l"(v));
}
__device__ __forceinline__ u64 add2(u64 a, u64 b) {
    u64 r; asm("add.rn.f32x2 %0,%1,%2;" : "=l"(r) : "l"(a), "l"(b)); return r;
}
__device__ __forceinline__ u64 mul2(u64 a, u64 b) {
    u64 r; asm("mul.rn.f32x2 %0,%1,%2;" : "=l"(r) : "l"(a), "l"(b)); return r;
}
__device__ __forceinline__ u64 fma2(u64 a, u64 b, u64 c) {
    u64 r; asm("fma.rn.f32x2 %0,%1,%2,%3;" : "=l"(r) : "l"(a), "l"(b), "l"(c)); return r;
}

// ---------- xnorm (+ zero of M/mu in block 0) ----------
__global__ __launch_bounds__(256) void k_xnorm(const float* __restrict__ loc) {
    int idx = blockIdx.x * 256 + threadIdx.x;
    int b = idx >> 14, n = idx & (N_ - 1);
    const float* lb = loc + (size_t)b * 3 * N_;
    g_xnorm[idx] = sq3_rn(lb[n], lb[N_ + n], lb[2 * N_ + n]);
    if (blockIdx.x == 0) {
        int t = threadIdx.x;
        for (int j = t; j < CH * CH; j += 256) g_M[j] = 0.f;
        if (t < CH) g_mu[t] = 0.f;
    }
}

// ---------- transpose fea -> [b][n][c] ----------
__global__ __launch_bounds__(256) void k_transpose(const float* __restrict__ fea) {
    __shared__ float t[32][33];
    int b = blockIdx.z, c0 = blockIdx.y * 32, n0 = blockIdx.x * 32;
    int tx = threadIdx.x, ty = threadIdx.y;
    const float* src = fea + ((size_t)b * CH + c0) * N_ + n0;
#pragma unroll
    for (int k = 0; k < 4; k++) t[ty + k * 8][tx] = src[(size_t)(ty + k * 8) * N_ + tx];
    __syncthreads();
    float* dst = g_feaT + ((size_t)b * N_ + n0) * CH + c0;
#pragma unroll
    for (int k = 0; k < 4; k++) dst[(size_t)(ty + k * 8) * CH + tx] = t[tx][ty + k * 8];
}

// ---------- second moments: 8x8 f32x2 tiling, k-split x4, smem merge ----------
__global__ __launch_bounds__(256) void k_moments() {
    extern __shared__ __align__(16) float s_m[];
    float* tile  = s_m;          // 8192 floats (32KB)
    float* sMred = s_m + 8192;   // 4096 floats (16KB)
    int blk = blockIdx.x;
    int b = blk >> 4;
    int p0 = (blk & 15) * 1024;
    int tid = threadIdx.x;
    int g = tid >> 6, t6 = tid & 63;
    int r0 = (t6 >> 3) << 3, c0 = (t6 & 7) << 3;
    u64 acc2[32];
#pragma unroll
    for (int i = 0; i < 32; i++) acc2[i] = 0ull;
    float mu = 0.f;
    for (int j = tid; j < 4096; j += 256) sMred[j] = 0.f;
    for (int t = 0; t < 8; t++) {
        __syncthreads();
        const float4* src = (const float4*)(g_feaT + ((size_t)(b * N_ + p0 + t * 128)) * CH);
        float4* dst4 = (float4*)tile;
        for (int j = tid; j < 2048; j += 256) dst4[j] = src[j];
        __syncthreads();
        int pbeg = g * 32;
        for (int p = pbeg; p < pbeg + 32; p++) {
            const float* row = tile + (p << 6);
            float4 a0 = *(const float4*)(row + r0);
            float4 a1 = *(const float4*)(row + r0 + 4);
            const u64* bp = (const u64*)(row + c0);
            u64 b0 = bp[0], b1 = bp[1], b2 = bp[2], b3 = bp[3];
            float ar[8] = {a0.x, a0.y, a0.z, a0.w, a1.x, a1.y, a1.z, a1.w};
#pragma unroll
            for (int i = 0; i < 8; i++) {
                u64 ai = pk2(ar[i], ar[i]);
                acc2[i * 4 + 0] = fma2(ai, b0, acc2[i * 4 + 0]);
                acc2[i * 4 + 1] = fma2(ai, b1, acc2[i * 4 + 1]);
                acc2[i * 4 + 2] = fma2(ai, b2, acc2[i * 4 + 2]);
                acc2[i * 4 + 3] = fma2(ai, b3, acc2[i * 4 + 3]);
            }
        }
        if (tid < CH)
            for (int p = 0; p < 128; p++) mu += tile[(p << 6) + tid];
    }
    __syncthreads();
    // merge the 4 k-groups into sMred (phased, no atomics)
    for (int g2 = 0; g2 < 4; g2++) {
        if (g == g2) {
#pragma unroll
            for (int i = 0; i < 8; i++)
#pragma unroll
                for (int j2 = 0; j2 < 4; j2++) {
                    float lo, hi; upk2(acc2[i * 4 + j2], lo, hi);
                    sMred[(r0 + i) * 64 + c0 + 2 * j2]     += lo;
                    sMred[(r0 + i) * 64 + c0 + 2 * j2 + 1] += hi;
                }
        }
        __syncthreads();
    }
    for (int j = tid; j < 4096; j += 256) atomicAdd(&g_M[j], sMred[j]);
    if (tid < CH) atomicAdd(&g_mu[tid], mu);
}

// ---------- FPS (round-12 proven) ----------
__global__ __launch_bounds__(512) void k_fps(const float* __restrict__ loc) {
    __shared__ u64 s_red[16];
    __shared__ int s_far;
    __shared__ int s_fidx[S_];
    int b = blockIdx.x, tid = threadIdx.x;
    const float* lx = loc + (size_t)b * 3 * N_;
    const float* ly = lx + N_;
    const float* lz = ly + N_;
    u64 pyp[16], pzp[16];
    float dist[32];
#pragma unroll
    for (int i = 0; i < 16; i++) {
        int n = 2 * tid + i * 1024;
        pyp[i] = *(const u64*)(ly + n);
        pzp[i] = *(const u64*)(lz + n);
        dist[2 * i] = 1e10f; dist[2 * i + 1] = 1e10f;
    }
    int far = 0;
    for (int s = 0; s < S_; s++) {
        if (tid == 0) s_fidx[s] = far;
        float cx = lx[far], cy = ly[far], cz = lz[far];
        u64 ncx = pk2(-cx, -cx), ncy = pk2(-cy, -cy), ncz = pk2(-cz, -cz);
        float bestd = -1.f; int bestn = 0;
#pragma unroll
        for (int i = 0; i < 16; i++) {
            int n = 2 * tid + i * 1024;
            u64 pxp = *(const u64*)(lx + n);
            u64 dx = add2(pxp, ncx), dy = add2(pyp[i], ncy), dz = add2(pzp[i], ncz);
            u64 sum = add2(add2(mul2(dx, dx), mul2(dy, dy)), mul2(dz, dz));
            float d0, d1; upk2(sum, d0, d1);
            float m0 = fminf(dist[2 * i], d0);     dist[2 * i] = m0;
            float m1 = fminf(dist[2 * i + 1], d1); dist[2 * i + 1] = m1;
            if (m0 > bestd) { bestd = m0; bestn = n; }
            if (m1 > bestd) { bestd = m1; bestn = n + 1; }
        }
        u64 key = ((u64)__float_as_uint(bestd) << 32) | (unsigned)(0xFFFFFFFFu - (unsigned)bestn);
#pragma unroll
        for (int off = 16; off; off >>= 1) {
            u64 o = __shfl_down_sync(0xffffffffu, key, off);
            if (o > key) key = o;
        }
        if ((tid & 31) == 0) s_red[tid >> 5] = key;
        __syncthreads();
        if (tid < 32) {
            u64 v = (tid < 16) ? s_red[tid] : 0ull;
#pragma unroll
            for (int off = 8; off; off >>= 1) {
                u64 o = __shfl_down_sync(0xffffffffu, v, off);
                if (o > v) v = o;
            }
            if (tid == 0) s_far = (int)(0xFFFFFFFFu - (unsigned)(v & 0xFFFFFFFFull));
        }
        __syncthreads();
        far = s_far;
    }
    if (tid < S_) {
        int n = s_fidx[tid];
        g_fploc[(b * S_ + tid) * 3 + 0] = lx[n];
        g_fploc[(b * S_ + tid) * 3 + 1] = ly[n];
        g_fploc[(b * S_ + tid) * 3 + 2] = lz[n];
    }
    __syncthreads();
    for (int j = tid; j < S_ * CH; j += 512) {
        int s = j >> 6, c = j & 63;
        g_fpfea[b * S_ * CH + j] = g_feaT[((size_t)(b * N_ + s_fidx[s])) * CH + c];
    }
}

// ---------- ball query (256 pts/iter) + node_offset ----------
__global__ __launch_bounds__(128) void k_ball(const float* __restrict__ loc,
                                              const float* __restrict__ w_off,
                                              float* __restrict__ out) {
    __shared__ int   s_idx[K_];
    __shared__ float s_fpf[CH];
    __shared__ float s_w[3 * CH];
    __shared__ float s_p[3];
    __shared__ int   s_cnt;
    __shared__ float s_part[2][3];
    int s = blockIdx.x, b = blockIdx.y, tid = threadIdx.x;
    int lane = tid & 31;
    for (int j = tid; j < 3 * CH; j += 128) s_w[j] = w_off[j];
    if (tid < CH) s_fpf[tid] = g_fpfea[(b * S_ + s) * CH + tid];
    if (tid < 3) s_p[tid] = g_fploc[(b * S_ + s) * 3 + tid];
    if (tid == 0) s_cnt = 0;
    __syncthreads();
    float px = s_p[0], py = s_p[1], pz = s_p[2];
    float pp = sq3_rn(px, py, pz);
    if (tid < 32) {
        const float R2 = 0.3f * 0.3f;
        const float* lx = loc + (size_t)b * 3 * N_;
        const float* ly = lx + N_;
        const float* lz = ly + N_;
        const float* xn = g_xnorm + b * N_;
        int cnt = 0;
        for (int base = 0; base < N_ && cnt < K_; base += 256) {
            int n0 = base + 8 * lane;
            float4 xv0 = *(const float4*)(lx + n0);
            float4 xv1 = *(const float4*)(lx + n0 + 4);
            float4 yv0 = *(const float4*)(ly + n0);
            float4 yv1 = *(const float4*)(ly + n0 + 4);
            float4 zv0 = *(const float4*)(lz + n0);
            float4 zv1 = *(const float4*)(lz + n0 + 4);
            float4 nv0 = *(const float4*)(xn + n0);
            float4 nv1 = *(const float4*)(xn + n0 + 4);
            unsigned inm = 0;
            {
                float xa[8] = {xv0.x, xv0.y, xv0.z, xv0.w, xv1.x, xv1.y, xv1.z, xv1.w};
                float ya[8] = {yv0.x, yv0.y, yv0.z, yv0.w, yv1.x, yv1.y, yv1.z, yv1.w};
                float za[8] = {zv0.x, zv0.y, zv0.z, zv0.w, zv1.x, zv1.y, zv1.z, zv1.w};
                float na[8] = {nv0.x, nv0.y, nv0.z, nv0.w, nv1.x, nv1.y, nv1.z, nv1.w};
#pragma unroll
                for (int j = 0; j < 8; j++) {
                    float dot = fmaf(pz, za[j], fmaf(py, ya[j], __fmul_rn(px, xa[j])));
                    bool in = !(__fadd_rn(__fadd_rn(__fmul_rn(-2.0f, dot), pp), na[j]) > R2);
                    inm |= ((unsigned)in) << j;
                }
            }
            int myc = __popc(inm);
            int scan = myc;
#pragma unroll
            for (int off = 1; off < 32; off <<= 1) {
                int t = __shfl_up_sync(0xffffffffu, scan, off);
                if (lane >= off) scan += t;
            }
            int total = __shfl_sync(0xffffffffu, scan, 31);
            int p = cnt + scan - myc;
#pragma unroll
            for (int j = 0; j < 8; j++) {
                if (inm & (1u << j)) { if (p < K_) s_idx[p] = n0 + j; p++; }
            }
            cnt += total;
        }
        if (tid == 0) s_cnt = cnt < K_ ? cnt : K_;
    }
    __syncthreads();
    int cnt = s_cnt;
    if (tid >= cnt && tid < K_) s_idx[tid] = s_idx[0];
    __syncthreads();
    float c0 = 0.f, c1 = 0.f, c2 = 0.f;
    if (tid < K_) {
        int n = s_idx[tid];
        const float4* fr = (const float4*)(g_feaT + ((size_t)(b * N_ + n)) * CH);
        float a0 = 0.f, a1 = 0.f, a2 = 0.f;
#pragma unroll
        for (int j = 0; j < 16; j++) {
            float4 f = fr[j];
            float g0 = f.x - s_fpf[4 * j + 0];
            float g1 = f.y - s_fpf[4 * j + 1];
            float g2 = f.z - s_fpf[4 * j + 2];
            float g3 = f.w - s_fpf[4 * j + 3];
            a0 = fmaf(s_w[4 * j + 0], g0, a0); a0 = fmaf(s_w[4 * j + 1], g1, a0);
            a0 = fmaf(s_w[4 * j + 2], g2, a0); a0 = fmaf(s_w[4 * j + 3], g3, a0);
            a1 = fmaf(s_w[CH + 4 * j + 0], g0, a1); a1 = fmaf(s_w[CH + 4 * j + 1], g1, a1);
            a1 = fmaf(s_w[CH + 4 * j + 2], g2, a1); a1 = fmaf(s_w[CH + 4 * j + 3], g3, a1);
            a2 = fmaf(s_w[2 * CH + 4 * j + 0], g0, a2); a2 = fmaf(s_w[2 * CH + 4 * j + 1], g1, a2);
            a2 = fmaf(s_w[2 * CH + 4 * j + 2], g2, a2); a2 = fmaf(s_w[2 * CH + 4 * j + 3], g3, a2);
        }
        float t0 = tanhf(a0), t1 = tanhf(a1), t2 = tanhf(a2);
        const float* lp = loc + (size_t)b * 3 * N_;
        c0 = t0 * (lp[n] - px);
        c1 = t1 * (lp[N_ + n] - py);
        c2 = t2 * (lp[2 * N_ + n] - pz);
    }
#pragma unroll
    for (int off = 16; off; off >>= 1) {
        c0 += __shfl_down_sync(0xffffffffu, c0, off);
        c1 += __shfl_down_sync(0xffffffffu, c1, off);
        c2 += __shfl_down_sync(0xffffffffu, c2, off);
    }
    if (tid < K_ && (tid & 31) == 0) {
        s_part[tid >> 5][0] = c0; s_part[tid >> 5][1] = c1; s_part[tid >> 5][2] = c2;
    }
    __syncthreads();
    if (tid == 0) {
        float o0 = (s_part[0][0] + s_part[1][0]) * 0.015625f;
        float o1 = (s_part[0][1] + s_part[1][1]) * 0.015625f;
        float o2 = (s_part[0][2] + s_part[1][2]) * 0.015625f;
        out[OUT2 + b * 3 * S_ + 0 * S_ + s] = o0;
        out[OUT2 + b * 3 * S_ + 1 * S_ + s] = o1;
        out[OUT2 + b * 3 * S_ + 2 * S_ + s] = o2;
        g_nodeloc[(b * S_ + s) * 3 + 0] = px + o0;
        g_nodeloc[(b * S_ + s) * 3 + 1] = py + o1;
        g_nodeloc[(b * S_ + s) * 3 + 2] = pz + o2;
    }
}

// ---------- BN constants + wT ----------
__global__ __launch_bounds__(256) void k_bn(const float* __restrict__ w,
                                            const float* __restrict__ b_res,
                                            const float* __restrict__ g_res,
                                            const float* __restrict__ be_res) {
    __shared__ float sM[CH * CH];
    __shared__ float sw[CH * CH];
    __shared__ float smu[CH];
    int tid = threadIdx.x;
    for (int j = tid; j < CH * CH; j += 256) { sM[j] = g_M[j]; sw[j] = w[j]; }
    if (tid < CH) smu[tid] = g_mu[tid];
    __syncthreads();
    const float invNp = 1.0f / (float)((size_t)B_ * N_);
    if (tid < CH) {
        int o = tid;
        float m1 = 0.f, ey2 = 0.f;
        for (int c = 0; c < CH; c++) {
            float wc = sw[o * CH + c];
            m1 = fmaf(wc, smu[c], m1);
            float r = 0.f;
            for (int c2 = 0; c2 < CH; c2++) r = fmaf(sw[o * CH + c2], sM[c * CH + c2], r);
            ey2 = fmaf(wc, r, ey2);
        }
        m1 *= invNp; ey2 *= invNp;
        float var = ey2 - m1 * m1;
        float meanY = m1 + b_res[o];
        float sc = rsqrtf(var + 1e-5f) * g_res[o];
        g_scale[o] = sc;
        g_shift[o] = fmaf(b_res[o] - meanY, sc, be_res[o]);
    }
    for (int j = tid; j < CH * CH; j += 256) {
        int c = j >> 6, o = j & 63;
        g_wT[c * CH + o] = sw[o * CH + c];
    }
}

// ---------- kNN-64 + fused GEMM/kmax/BN/relu ----------
__global__ __launch_bounds__(256) void k_knn(const float* __restrict__ loc,
                                             float* __restrict__ out) {
    extern __shared__ float s_dyn[];               // 64KB
    unsigned* s_keys = (unsigned*)s_dyn;
    __shared__ unsigned short s_h[8][16];
    __shared__ unsigned sPref;
    __shared__ int sWant, sC1, sCT;
    __shared__ int s_out[K_];
    __shared__ int s_tie[128];
    __shared__ float s_red[4 * CH];
    int s = blockIdx.x, b = blockIdx.y, tid = threadIdx.x;
    int lane = tid & 31, wid = tid >> 5;
    float qx = g_nodeloc[(b * S_ + s) * 3 + 0];
    float qy = g_nodeloc[(b * S_ + s) * 3 + 1];
    float qz = g_nodeloc[(b * S_ + s) * 3 + 2];
    float qq = sq3_rn(qx, qy, qz);
    const float* lx = loc + (size_t)b * 3 * N_;
    const float* ly = lx + N_;
    const float* lz = ly + N_;
    const float* xn = g_xnorm + b * N_;
    u64 qx2 = pk2(qx, qx), qy2 = pk2(qy, qy), qz2 = pk2(qz, qz);
    u64 qq2 = pk2(qq, qq), m2 = pk2(-2.0f, -2.0f);
    for (int i = 0; i < 32; i++) {
        int n = 2 * (tid + i * 256);
        u64 lxp = *(const u64*)(lx + n);
        u64 lyp = *(const u64*)(ly + n);
        u64 lzp = *(const u64*)(lz + n);
        u64 dot = fma2(qz2, lzp, fma2(qy2, lyp, mul2(qx2, lxp)));
        u64 d = add2(add2(mul2(m2, dot), qq2), *(const u64*)(xn + n));
        float d0, d1; upk2(d, d0, d1);
        unsigned u0 = __float_as_uint(d0);
        u0 = (u0 & 0x80000000u) ? ~u0 : (u0 | 0x80000000u);
        unsigned u1 = __float_as_uint(d1);
        u1 = (u1 & 0x80000000u) ? ~u1 : (u1 | 0x80000000u);
        *(u64*)(s_keys + n) = ((u64)u1 << 32) | u0;
    }
    if (tid == 0) { sPref = 0u; sWant = K_; sC1 = 0; sCT = 0; }
    __syncthreads();
    for (int p = 7; p >= 0; p--) {
        int sh = p * 4;
        unsigned himask = (p == 7) ? 0u : (0xFFFFFFFFu << (sh + 4));
        unsigned pref = sPref;
        u64 clo = 0ull, chi = 0ull;
        for (int i = 0; i < 64; i++) {
            unsigned k = s_keys[tid + i * 256];
            if ((k & himask) == pref) {
                unsigned d4 = (k >> sh) & 15u;
                u64 inc = 1ull << ((d4 & 7u) * 8u);
                if (d4 < 8u) clo += inc; else chi += inc;
            }
        }
        const u64 M0 = 0x00FF00FF00FF00FFull;
        u64 e0 = clo & M0, e1 = (clo >> 8) & M0;
        u64 e2 = chi & M0, e3 = (chi >> 8) & M0;
#pragma unroll
        for (int off = 16; off; off >>= 1) {
            e0 += __shfl_down_sync(0xffffffffu, e0, off);
            e1 += __shfl_down_sync(0xffffffffu, e1, off);
            e2 += __shfl_down_sync(0xffffffffu, e2, off);
            e3 += __shfl_down_sync(0xffffffffu, e3, off);
        }
        if (lane == 0) {
#pragma unroll
            for (int j = 0; j < 4; j++) {
                s_h[wid][2 * j]     = (unsigned short)((e0 >> (16 * j)) & 0xFFFFull);
                s_h[wid][2 * j + 1] = (unsigned short)((e1 >> (16 * j)) & 0xFFFFull);
                s_h[wid][8 + 2 * j] = (unsigned short)((e2 >> (16 * j)) & 0xFFFFull);
                s_h[wid][9 + 2 * j] = (unsigned short)((e3 >> (16 * j)) & 0xFFFFull);
            }
        }
        __syncthreads();
        if (tid < 16) {
            int c = 0;
#pragma unroll
            for (int w = 0; w < 8; w++) c += (int)s_h[w][tid];
            int inc = c;
#pragma unroll
            for (int off = 1; off < 16; off <<= 1) {
                int t = __shfl_up_sync(0x0000FFFFu, inc, off);
                if (lane >= off) inc += t;
            }
            int excl = inc - c;
            int want = sWant;
            if (excl < want && want <= inc) {
                sPref = pref | ((unsigned)tid << sh);
                sWant = want - excl;
            }
        }
        __syncthreads();
    }
    unsigned pivot = sPref;
    int need = sWant;
    for (int i = 0; i < 64; i++) {
        int n = tid + i * 256;
        unsigned k = s_keys[n];
        if (k < pivot) { int p0 = atomicAdd(&sC1, 1); s_out[p0] = n; }
        else if (k == pivot) { int p0 = atomicAdd(&sCT, 1); if (p0 < 128) s_tie[p0] = n; }
    }
    __syncthreads();
    if (tid == 0) {
        int c1 = sC1, nt = sCT; if (nt > 128) nt = 128;
        for (int j = 0; j < need; j++) {
            int bi = -1, bv = 0x7fffffff;
            for (int t = 0; t < nt; t++) { int v2 = s_tie[t]; if (v2 >= 0 && v2 < bv) { bv = v2; bi = t; } }
            s_out[c1 + j] = bv;
            if (bi >= 0) s_tie[bi] = -1;
        }
    }
    __syncthreads();
    float* xg = s_dyn;                 // [64][64]
    float* sWT = s_dyn + 4096;         // [c][o]
    for (int j = tid; j < 1024; j += 256) {
        int r = j >> 4, c4 = j & 15;
        float4 f = ((const float4*)(g_feaT + ((size_t)(b * N_ + s_out[r])) * CH))[c4];
        ((float4*)xg)[j] = f;
        ((float4*)sWT)[j] = ((const float4*)g_wT)[j];
    }
    __syncthreads();
    int o = tid & 63, kseg = tid >> 6;
    u64 wp[32];
#pragma unroll
    for (int c = 0; c < 32; c++) wp[c] = pk2(sWT[(2 * c) * 64 + o], sWT[(2 * c + 1) * 64 + o]);
    float mx = -3.4e38f;
    for (int k = kseg * 16; k < kseg * 16 + 16; k++) {
        const ulonglong2* xr = (const ulonglong2*)(xg + (k << 6));
        u64 acc2 = 0ull;
#pragma unroll
        for (int c4 = 0; c4 < 16; c4++) {
            ulonglong2 f = xr[c4];
            acc2 = fma2(wp[2 * c4], f.x, acc2);
            acc2 = fma2(wp[2 * c4 + 1], f.y, acc2);
        }
        float alo, ahi; upk2(acc2, alo, ahi);
        mx = fmaxf(mx, alo + ahi);
    }
    s_red[kseg * 64 + o] = mx;
    __syncthreads();
    if (tid < 64) {
        float m = fmaxf(fmaxf(s_red[tid], s_red[64 + tid]), fmaxf(s_red[128 + tid], s_red[192 + tid]));
        float val = fmaxf(fmaf(m, g_scale[tid], g_shift[tid]), 0.f);
        out[OUT1 + (b * CH + tid) * S_ + s] = val;
    }
}

// ---------- upsample ----------
__global__ __launch_bounds__(256) void k_up(const float* __restrict__ loc,
                                            const float* __restrict__ fea,
                                            float* __restrict__ out) {
    __shared__ float nx[64], ny[64], nz[64], nn[64];
    __shared__ float nf[64 * 65];
    int b = blockIdx.y, n0 = blockIdx.x * 256, tid = threadIdx.x;
    if (tid < 64) {
        float x = g_nodeloc[(b * S_ + tid) * 3 + 0];
        float y = g_nodeloc[(b * S_ + tid) * 3 + 1];
        float z = g_nodeloc[(b * S_ + tid) * 3 + 2];
        nx[tid] = x; ny[tid] = y; nz[tid] = z; nn[tid] = sq3_rn(x, y, z);
    }
    for (int j = tid; j < 64 * 64; j += 256) {
        int c = j >> 6, s2 = j & 63;
        nf[c * 65 + s2] = out[OUT1 + (b * CH + c) * S_ + s2];
    }
    __syncthreads();
    int n = n0 + tid;
    const float* lp = loc + (size_t)b * 3 * N_;
    float px = lp[n], py = lp[N_ + n], pz = lp[2 * N_ + n];
    float pn = g_xnorm[b * N_ + n];
    float d0 = 3.4e38f, d1 = 3.4e38f, d2 = 3.4e38f;
    int i0 = 0, i1 = 0, i2 = 0;
    for (int s2 = 0; s2 < 64; s2++) {
        float dot = fmaf(pz, nz[s2], fmaf(py, ny[s2], __fmul_rn(px, nx[s2])));
        float d = __fadd_rn(__fadd_rn(__fmul_rn(-2.0f, dot), pn), nn[s2]);
        if (d < d0)      { d2 = d1; i2 = i1; d1 = d0; i1 = i0; d0 = d; i0 = s2; }
        else if (d < d1) { d2 = d1; i2 = i1; d1 = d; i1 = s2; }
        else if (d < d2) { d2 = d; i2 = s2; }
    }
    float w0 = 1.0f / fmaxf(d0, 1e-10f);
    float w1 = 1.0f / fmaxf(d1, 1e-10f);
    float w2 = 1.0f / fmaxf(d2, 1e-10f);
    float ws = __fadd_rn(__fadd_rn(w0, w1), w2);
    w0 /= ws; w1 /= ws; w2 /= ws;
    const float* fb = fea + (size_t)b * CH * N_ + n;
    float* ob = out + (size_t)b * 128 * N_ + n;
#pragma unroll 8
    for (int c = 0; c < 64; c++) ob[(size_t)c * N_] = fb[(size_t)c * N_];
#pragma unroll 8
    for (int c = 0; c < 64; c++) {
        float v = fmaf(nf[c * 65 + i2], w2, fmaf(nf[c * 65 + i1], w1, __fmul_rn(nf[c * 65 + i0], w0)));
        ob[(size_t)(64 + c) * N_] = v;
    }
}

extern "C" void kernel_launch(void* const* d_in, const int* in_sizes, int n_in,
                              void* d_out, int out_size) {
    const float* fea    = (const float*)d_in[0];
    const float* loc    = (const float*)d_in[1];
    const float* w_res  = (const float*)d_in[2];
    const float* b_res  = (const float*)d_in[3];
    const float* g_res  = (const float*)d_in[4];
    const float* be_res = (const float*)d_in[5];
    const float* w_off  = (const float*)d_in[6];
    float* out = (float*)d_out;

    cudaFuncSetAttribute(k_knn, cudaFuncAttributeMaxDynamicSharedMemorySize, 65536);
    cudaFuncSetAttribute(k_moments, cudaFuncAttributeMaxDynamicSharedMemorySize, 49152);

    k_xnorm<<<(B_ * N_) / 256, 256>>>(loc);
    k_transpose<<<dim3(N_ / 32, CH / 32, B_), dim3(32, 8)>>>(fea);
    k_moments<<<256, 256, 49152>>>();
    k_fps<<<B_, 512>>>(loc);
    k_ball<<<dim3(S_, B_), 128>>>(loc, w_off, out);
    k_bn<<<1, 256>>>(w_res, b_res, g_res, be_res);
    k_knn<<<dim3(S_, B_), 256, 65536>>>(loc, out);
    k_up<<<dim3(N_ / 256, B_), 256>>>(loc, fea, out);
}

// round 16
// speedup vs baseline: 1.3771x; 1.0346x over previous
#include <cuda_runtime.h>
#include <cuda_bf16.h>
#include <cstdint>

#define B_ 16
#define N_ 16384
#define CH 64
#define S_ 64
#define K_ 64
#define OUT1 (B_*128*N_)
#define OUT2 (OUT1 + B_*CH*S_)

typedef unsigned long long u64;

__device__ float g_feaT[(size_t)B_ * N_ * CH];
__device__ float g_xnorm[B_ * N_];
__device__ float g_fploc[B_ * S_ * 3];
__device__ float g_fpfea[B_ * S_ * CH];
__device__ float g_nodeloc[B_ * S_ * 3];
__device__ float g_M[CH * CH];
__device__ float g_mu[CH];
__device__ float g_scale[CH];
__device__ float g_shift[CH];
__device__ float g_wT[CH * CH];

__device__ __forceinline__ float sq3_rn(float x, float y, float z) {
    return __fadd_rn(__fadd_rn(__fmul_rn(x, x), __fmul_rn(y, y)), __fmul_rn(z, z));
}
__device__ __forceinline__ u64 pk2(float lo, float hi) {
    u64 r; asm("mov.b64 %0,{%1,%2};" : "=l"(r) : "f"(lo), "f"(hi)); return r;
}
__device__ __forceinline__ void upk2(u64 v, float& lo, float& hi) {
    asm("mov.b64 {%0,%1},%2;" : "=f"(lo), "=f"(hi) : "l"(v));
}
__device__ __forceinline__ u64 add2(u64 a, u64 b) {
    u64 r; asm("add.rn.f32x2 %0,%1,%2;" : "=l"(r) : "l"(a), "l"(b)); return r;
}
__device__ __forceinline__ u64 mul2(u64 a, u64 b) {
    u64 r; asm("mul.rn.f32x2 %0,%1,%2;" : "=l"(r) : "l"(a), "l"(b)); return r;
}
__device__ __forceinline__ u64 fma2(u64 a, u64 b, u64 c) {
    u64 r; asm("fma.rn.f32x2 %0,%1,%2,%3;" : "=l"(r) : "l"(a), "l"(b), "l"(c)); return r;
}

// ---------- xnorm (+ zero of M/mu in block 0) ----------
__global__ __launch_bounds__(256) void k_xnorm(const float* __restrict__ loc) {
    int idx = blockIdx.x * 256 + threadIdx.x;
    int b = idx >> 14, n = idx & (N_ - 1);
    const float* lb = loc + (size_t)b * 3 * N_;
    g_xnorm[idx] = sq3_rn(lb[n], lb[N_ + n], lb[2 * N_ + n]);
    if (blockIdx.x == 0) {
        int t = threadIdx.x;
        for (int j = t; j < CH * CH; j += 256) g_M[j] = 0.f;
        if (t < CH) g_mu[t] = 0.f;
    }
}

// ---------- transpose fea -> [b][n][c] ----------
__global__ __launch_bounds__(256) void k_transpose(const float* __restrict__ fea) {
    __shared__ float t[32][33];
    int b = blockIdx.z, c0 = blockIdx.y * 32, n0 = blockIdx.x * 32;
    int tx = threadIdx.x, ty = threadIdx.y;
    const float* src = fea + ((size_t)b * CH + c0) * N_ + n0;
#pragma unroll
    for (int k = 0; k < 4; k++) t[ty + k * 8][tx] = src[(size_t)(ty + k * 8) * N_ + tx];
    __syncthreads();
    float* dst = g_feaT + ((size_t)b * N_ + n0) * CH + c0;
#pragma unroll
    for (int k = 0; k < 4; k++) dst[(size_t)(ty + k * 8) * CH + tx] = t[tx][ty + k * 8];
}

// ---------- FPS: 1024 threads, 16 pts/thread, registers only ----------
__global__ __launch_bounds__(1024) void k_fps(const float* __restrict__ loc) {
    __shared__ u64 s_red[32];
    __shared__ int s_far;
    __shared__ int s_fidx[S_];
    int b = blockIdx.x, tid = threadIdx.x;
    const float* lx = loc + (size_t)b * 3 * N_;
    const float* ly = lx + N_;
    const float* lz = ly + N_;
    u64 pyp[8], pzp[8];
    float dist[16];
#pragma unroll
    for (int i = 0; i < 8; i++) {
        int n = 2 * tid + i * 2048;
        pyp[i] = *(const u64*)(ly + n);
        pzp[i] = *(const u64*)(lz + n);
        dist[2 * i] = 1e10f; dist[2 * i + 1] = 1e10f;
    }
    int far = 0;
    for (int s = 0; s < S_; s++) {
        if (tid == 0) s_fidx[s] = far;
        float cx = lx[far], cy = ly[far], cz = lz[far];
        u64 ncx = pk2(-cx, -cx), ncy = pk2(-cy, -cy), ncz = pk2(-cz, -cz);
        float bestd = -1.f; int bestn = 0;
#pragma unroll
        for (int i = 0; i < 8; i++) {
            int n = 2 * tid + i * 2048;
            u64 pxp = *(const u64*)(lx + n);
            u64 dx = add2(pxp, ncx), dy = add2(pyp[i], ncy), dz = add2(pzp[i], ncz);
            u64 sum = add2(add2(mul2(dx, dx), mul2(dy, dy)), mul2(dz, dz));
            float d0, d1; upk2(sum, d0, d1);
            float m0 = fminf(dist[2 * i], d0);     dist[2 * i] = m0;
            float m1 = fminf(dist[2 * i + 1], d1); dist[2 * i + 1] = m1;
            if (m0 > bestd) { bestd = m0; bestn = n; }
            if (m1 > bestd) { bestd = m1; bestn = n + 1; }
        }
        u64 key = ((u64)__float_as_uint(bestd) << 32) | (unsigned)(0xFFFFFFFFu - (unsigned)bestn);
#pragma unroll
        for (int off = 16; off; off >>= 1) {
            u64 o = __shfl_down_sync(0xffffffffu, key, off);
            if (o > key) key = o;
        }
        if ((tid & 31) == 0) s_red[tid >> 5] = key;
        __syncthreads();
        if (tid < 32) {
            u64 v = s_red[tid];
#pragma unroll
            for (int off = 16; off; off >>= 1) {
                u64 o = __shfl_down_sync(0xffffffffu, v, off);
                if (o > v) v = o;
            }
            if (tid == 0) s_far = (int)(0xFFFFFFFFu - (unsigned)(v & 0xFFFFFFFFull));
        }
        __syncthreads();
        far = s_far;
    }
    if (tid < S_) {
        int n = s_fidx[tid];
        g_fploc[(b * S_ + tid) * 3 + 0] = lx[n];
        g_fploc[(b * S_ + tid) * 3 + 1] = ly[n];
        g_fploc[(b * S_ + tid) * 3 + 2] = lz[n];
    }
    __syncthreads();
    for (int j = tid; j < S_ * CH; j += 1024) {
        int s = j >> 6, c = j & 63;
        g_fpfea[b * S_ * CH + j] = g_feaT[((size_t)(b * N_ + s_fidx[s])) * CH + c];
    }
}

// ---------- second moments: 8x8 f32x2 tiling, k-split x4, smem merge ----------
__global__ __launch_bounds__(256) void k_moments() {
    extern __shared__ __align__(16) float s_m[];
    float* tile  = s_m;          // 8192 floats (32KB)
    float* sMred = s_m + 8192;   // 4096 floats (16KB)
    int blk = blockIdx.x;
    int b = blk >> 4;
    int p0 = (blk & 15) * 1024;
    int tid = threadIdx.x;
    int g = tid >> 6, t6 = tid & 63;
    int r0 = (t6 >> 3) << 3, c0 = (t6 & 7) << 3;
    u64 acc2[32];
#pragma unroll
    for (int i = 0; i < 32; i++) acc2[i] = 0ull;
    float mu = 0.f;
    for (int j = tid; j < 4096; j += 256) sMred[j] = 0.f;
    for (int t = 0; t < 8; t++) {
        __syncthreads();
        const float4* src = (const float4*)(g_feaT + ((size_t)(b * N_ + p0 + t * 128)) * CH);
        float4* dst4 = (float4*)tile;
        for (int j = tid; j < 2048; j += 256) dst4[j] = src[j];
        __syncthreads();
        int pbeg = g * 32;
        for (int p = pbeg; p < pbeg + 32; p++) {
            const float* row = tile + (p << 6);
            float4 a0 = *(const float4*)(row + r0);
            float4 a1 = *(const float4*)(row + r0 + 4);
            const u64* bp = (const u64*)(row + c0);
            u64 b0 = bp[0], b1 = bp[1], b2 = bp[2], b3 = bp[3];
            float ar[8] = {a0.x, a0.y, a0.z, a0.w, a1.x, a1.y, a1.z, a1.w};
#pragma unroll
            for (int i = 0; i < 8; i++) {
                u64 ai = pk2(ar[i], ar[i]);
                acc2[i * 4 + 0] = fma2(ai, b0, acc2[i * 4 + 0]);
                acc2[i * 4 + 1] = fma2(ai, b1, acc2[i * 4 + 1]);
                acc2[i * 4 + 2] = fma2(ai, b2, acc2[i * 4 + 2]);
                acc2[i * 4 + 3] = fma2(ai, b3, acc2[i * 4 + 3]);
            }
        }
        if (tid < CH)
            for (int p = 0; p < 128; p++) mu += tile[(p << 6) + tid];
    }
    __syncthreads();
    for (int g2 = 0; g2 < 4; g2++) {
        if (g == g2) {
#pragma unroll
            for (int i = 0; i < 8; i++)
#pragma unroll
                for (int j2 = 0; j2 < 4; j2++) {
                    float lo, hi; upk2(acc2[i * 4 + j2], lo, hi);
                    sMred[(r0 + i) * 64 + c0 + 2 * j2]     += lo;
                    sMred[(r0 + i) * 64 + c0 + 2 * j2 + 1] += hi;
                }
        }
        __syncthreads();
    }
    for (int j = tid; j < 4096; j += 256) atomicAdd(&g_M[j], sMred[j]);
    if (tid < CH) atomicAdd(&g_mu[tid], mu);
}

// ---------- ball query (256 pts/iter) + node_offset ----------
__global__ __launch_bounds__(128) void k_ball(const float* __restrict__ loc,
                                              const float* __restrict__ w_off,
                                              float* __restrict__ out) {
    __shared__ int   s_idx[K_];
    __shared__ float s_fpf[CH];
    __shared__ float s_w[3 * CH];
    __shared__ float s_p[3];
    __shared__ int   s_cnt;
    __shared__ float s_part[2][3];
    int s = blockIdx.x, b = blockIdx.y, tid = threadIdx.x;
    int lane = tid & 31;
    for (int j = tid; j < 3 * CH; j += 128) s_w[j] = w_off[j];
    if (tid < CH) s_fpf[tid] = g_fpfea[(b * S_ + s) * CH + tid];
    if (tid < 3) s_p[tid] = g_fploc[(b * S_ + s) * 3 + tid];
    if (tid == 0) s_cnt = 0;
    __syncthreads();
    float px = s_p[0], py = s_p[1], pz = s_p[2];
    float pp = sq3_rn(px, py, pz);
    if (tid < 32) {
        const float R2 = 0.3f * 0.3f;
        const float* lx = loc + (size_t)b * 3 * N_;
        const float* ly = lx + N_;
        const float* lz = ly + N_;
        const float* xn = g_xnorm + b * N_;
        int cnt = 0;
        for (int base = 0; base < N_ && cnt < K_; base += 256) {
            int n0 = base + 8 * lane;
            float4 xv0 = *(const float4*)(lx + n0);
            float4 xv1 = *(const float4*)(lx + n0 + 4);
            float4 yv0 = *(const float4*)(ly + n0);
            float4 yv1 = *(const float4*)(ly + n0 + 4);
            float4 zv0 = *(const float4*)(lz + n0);
            float4 zv1 = *(const float4*)(lz + n0 + 4);
            float4 nv0 = *(const float4*)(xn + n0);
            float4 nv1 = *(const float4*)(xn + n0 + 4);
            unsigned inm = 0;
            {
                float xa[8] = {xv0.x, xv0.y, xv0.z, xv0.w, xv1.x, xv1.y, xv1.z, xv1.w};
                float ya[8] = {yv0.x, yv0.y, yv0.z, yv0.w, yv1.x, yv1.y, yv1.z, yv1.w};
                float za[8] = {zv0.x, zv0.y, zv0.z, zv0.w, zv1.x, zv1.y, zv1.z, zv1.w};
                float na[8] = {nv0.x, nv0.y, nv0.z, nv0.w, nv1.x, nv1.y, nv1.z, nv1.w};
#pragma unroll
                for (int j = 0; j < 8; j++) {
                    float dot = fmaf(pz, za[j], fmaf(py, ya[j], __fmul_rn(px, xa[j])));
                    bool in = !(__fadd_rn(__fadd_rn(__fmul_rn(-2.0f, dot), pp), na[j]) > R2);
                    inm |= ((unsigned)in) << j;
                }
            }
            int myc = __popc(inm);
            int scan = myc;
#pragma unroll
            for (int off = 1; off < 32; off <<= 1) {
                int t = __shfl_up_sync(0xffffffffu, scan, off);
                if (lane >= off) scan += t;
            }
            int total = __shfl_sync(0xffffffffu, scan, 31);
            int p = cnt + scan - myc;
#pragma unroll
            for (int j = 0; j < 8; j++) {
                if (inm & (1u << j)) { if (p < K_) s_idx[p] = n0 + j; p++; }
            }
            cnt += total;
        }
        if (tid == 0) s_cnt = cnt < K_ ? cnt : K_;
    }
    __syncthreads();
    int cnt = s_cnt;
    if (tid >= cnt && tid < K_) s_idx[tid] = s_idx[0];
    __syncthreads();
    float c0 = 0.f, c1 = 0.f, c2 = 0.f;
    if (tid < K_) {
        int n = s_idx[tid];
        const float4* fr = (const float4*)(g_feaT + ((size_t)(b * N_ + n)) * CH);
        float a0 = 0.f, a1 = 0.f, a2 = 0.f;
#pragma unroll
        for (int j = 0; j < 16; j++) {
            float4 f = fr[j];
            float g0 = f.x - s_fpf[4 * j + 0];
            float g1 = f.y - s_fpf[4 * j + 1];
            float g2 = f.z - s_fpf[4 * j + 2];
            float g3 = f.w - s_fpf[4 * j + 3];
            a0 = fmaf(s_w[4 * j + 0], g0, a0); a0 = fmaf(s_w[4 * j + 1], g1, a0);
            a0 = fmaf(s_w[4 * j + 2], g2, a0); a0 = fmaf(s_w[4 * j + 3], g3, a0);
            a1 = fmaf(s_w[CH + 4 * j + 0], g0, a1); a1 = fmaf(s_w[CH + 4 * j + 1], g1, a1);
            a1 = fmaf(s_w[CH + 4 * j + 2], g2, a1); a1 = fmaf(s_w[CH + 4 * j + 3], g3, a1);
            a2 = fmaf(s_w[2 * CH + 4 * j + 0], g0, a2); a2 = fmaf(s_w[2 * CH + 4 * j + 1], g1, a2);
            a2 = fmaf(s_w[2 * CH + 4 * j + 2], g2, a2); a2 = fmaf(s_w[2 * CH + 4 * j + 3], g3, a2);
        }
        float t0 = tanhf(a0), t1 = tanhf(a1), t2 = tanhf(a2);
        const float* lp = loc + (size_t)b * 3 * N_;
        c0 = t0 * (lp[n] - px);
        c1 = t1 * (lp[N_ + n] - py);
        c2 = t2 * (lp[2 * N_ + n] - pz);
    }
#pragma unroll
    for (int off = 16; off; off >>= 1) {
        c0 += __shfl_down_sync(0xffffffffu, c0, off);
        c1 += __shfl_down_sync(0xffffffffu, c1, off);
        c2 += __shfl_down_sync(0xffffffffu, c2, off);
    }
    if (tid < K_ && (tid & 31) == 0) {
        s_part[tid >> 5][0] = c0; s_part[tid >> 5][1] = c1; s_part[tid >> 5][2] = c2;
    }
    __syncthreads();
    if (tid == 0) {
        float o0 = (s_part[0][0] + s_part[1][0]) * 0.015625f;
        float o1 = (s_part[0][1] + s_part[1][1]) * 0.015625f;
        float o2 = (s_part[0][2] + s_part[1][2]) * 0.015625f;
        out[OUT2 + b * 3 * S_ + 0 * S_ + s] = o0;
        out[OUT2 + b * 3 * S_ + 1 * S_ + s] = o1;
        out[OUT2 + b * 3 * S_ + 2 * S_ + s] = o2;
        g_nodeloc[(b * S_ + s) * 3 + 0] = px + o0;
        g_nodeloc[(b * S_ + s) * 3 + 1] = py + o1;
        g_nodeloc[(b * S_ + s) * 3 + 2] = pz + o2;
    }
}

// ---------- BN constants + wT ----------
__global__ __launch_bounds__(256) void k_bn(const float* __restrict__ w,
                                            const float* __restrict__ b_res,
                                            const float* __restrict__ g_res,
                                            const float* __restrict__ be_res) {
    __shared__ float sM[CH * CH];
    __shared__ float sw[CH * CH];
    __shared__ float smu[CH];
    int tid = threadIdx.x;
    for (int j = tid; j < CH * CH; j += 256) { sM[j] = g_M[j]; sw[j] = w[j]; }
    if (tid < CH) smu[tid] = g_mu[tid];
    __syncthreads();
    const float invNp = 1.0f / (float)((size_t)B_ * N_);
    if (tid < CH) {
        int o = tid;
        float m1 = 0.f, ey2 = 0.f;
        for (int c = 0; c < CH; c++) {
            float wc = sw[o * CH + c];
            m1 = fmaf(wc, smu[c], m1);
            float r = 0.f;
            for (int c2 = 0; c2 < CH; c2++) r = fmaf(sw[o * CH + c2], sM[c * CH + c2], r);
            ey2 = fmaf(wc, r, ey2);
        }
        m1 *= invNp; ey2 *= invNp;
        float var = ey2 - m1 * m1;
        float meanY = m1 + b_res[o];
        float sc = rsqrtf(var + 1e-5f) * g_res[o];
        g_scale[o] = sc;
        g_shift[o] = fmaf(b_res[o] - meanY, sc, be_res[o]);
    }
    for (int j = tid; j < CH * CH; j += 256) {
        int c = j >> 6, o = j & 63;
        g_wT[c * CH + o] = sw[o * CH + c];
    }
}

// ---------- kNN-64 + fused GEMM/kmax/BN/relu ----------
__global__ __launch_bounds__(256) void k_knn(const float* __restrict__ loc,
                                             float* __restrict__ out) {
    extern __shared__ float s_dyn[];               // 64KB
    unsigned* s_keys = (unsigned*)s_dyn;
    __shared__ unsigned short s_h[8][16];
    __shared__ unsigned sPref;
    __shared__ int sWant, sC1, sCT;
    __shared__ int s_out[K_];
    __shared__ int s_tie[128];
    __shared__ float s_red[4 * CH];
    int s = blockIdx.x, b = blockIdx.y, tid = threadIdx.x;
    int lane = tid & 31, wid = tid >> 5;
    float qx = g_nodeloc[(b * S_ + s) * 3 + 0];
    float qy = g_nodeloc[(b * S_ + s) * 3 + 1];
    float qz = g_nodeloc[(b * S_ + s) * 3 + 2];
    float qq = sq3_rn(qx, qy, qz);
    const float* lx = loc + (size_t)b * 3 * N_;
    const float* ly = lx + N_;
    const float* lz = ly + N_;
    const float* xn = g_xnorm + b * N_;
    u64 qx2 = pk2(qx, qx), qy2 = pk2(qy, qy), qz2 = pk2(qz, qz);
    u64 qq2 = pk2(qq, qq), m2 = pk2(-2.0f, -2.0f);
    for (int i = 0; i < 32; i++) {
        int n = 2 * (tid + i * 256);
        u64 lxp = *(const u64*)(lx + n);
        u64 lyp = *(const u64*)(ly + n);
        u64 lzp = *(const u64*)(lz + n);
        u64 dot = fma2(qz2, lzp, fma2(qy2, lyp, mul2(qx2, lxp)));
        u64 d = add2(add2(mul2(m2, dot), qq2), *(const u64*)(xn + n));
        float d0, d1; upk2(d, d0, d1);
        unsigned u0 = __float_as_uint(d0);
        u0 = (u0 & 0x80000000u) ? ~u0 : (u0 | 0x80000000u);
        unsigned u1 = __float_as_uint(d1);
        u1 = (u1 & 0x80000000u) ? ~u1 : (u1 | 0x80000000u);
        *(u64*)(s_keys + n) = ((u64)u1 << 32) | u0;
    }
    if (tid == 0) { sPref = 0u; sWant = K_; sC1 = 0; sCT = 0; }
    __syncthreads();
    for (int p = 7; p >= 0; p--) {
        int sh = p * 4;
        unsigned himask = (p == 7) ? 0u : (0xFFFFFFFFu << (sh + 4));
        unsigned pref = sPref;
        u64 clo = 0ull, chi = 0ull;
        for (int i = 0; i < 64; i++) {
            unsigned k = s_keys[tid + i * 256];
            if ((k & himask) == pref) {
                unsigned d4 = (k >> sh) & 15u;
                u64 inc = 1ull << ((d4 & 7u) * 8u);
                if (d4 < 8u) clo += inc; else chi += inc;
            }
        }
        const u64 M0 = 0x00FF00FF00FF00FFull;
        u64 e0 = clo & M0, e1 = (clo >> 8) & M0;
        u64 e2 = chi & M0, e3 = (chi >> 8) & M0;
#pragma unroll
        for (int off = 16; off; off >>= 1) {
            e0 += __shfl_down_sync(0xffffffffu, e0, off);
            e1 += __shfl_down_sync(0xffffffffu, e1, off);
            e2 += __shfl_down_sync(0xffffffffu, e2, off);
            e3 += __shfl_down_sync(0xffffffffu, e3, off);
        }
        if (lane == 0) {
#pragma unroll
            for (int j = 0; j < 4; j++) {
                s_h[wid][2 * j]     = (unsigned short)((e0 >> (16 * j)) & 0xFFFFull);
                s_h[wid][2 * j + 1] = (unsigned short)((e1 >> (16 * j)) & 0xFFFFull);
                s_h[wid][8 + 2 * j] = (unsigned short)((e2 >> (16 * j)) & 0xFFFFull);
                s_h[wid][9 + 2 * j] = (unsigned short)((e3 >> (16 * j)) & 0xFFFFull);
            }
        }
        __syncthreads();
        if (tid < 16) {
            int c = 0;
#pragma unroll
            for (int w = 0; w < 8; w++) c += (int)s_h[w][tid];
            int inc = c;
#pragma unroll
            for (int off = 1; off < 16; off <<= 1) {
                int t = __shfl_up_sync(0x0000FFFFu, inc, off);
                if (lane >= off) inc += t;
            }
            int excl = inc - c;
            int want = sWant;
            if (excl < want && want <= inc) {
                sPref = pref | ((unsigned)tid << sh);
                sWant = want - excl;
            }
        }
        __syncthreads();
    }
    unsigned pivot = sPref;
    int need = sWant;
    for (int i = 0; i < 64; i++) {
        int n = tid + i * 256;
        unsigned k = s_keys[n];
        if (k < pivot) { int p0 = atomicAdd(&sC1, 1); s_out[p0] = n; }
        else if (k == pivot) { int p0 = atomicAdd(&sCT, 1); if (p0 < 128) s_tie[p0] = n; }
    }
    __syncthreads();
    if (tid == 0) {
        int c1 = sC1, nt = sCT; if (nt > 128) nt = 128;
        for (int j = 0; j < need; j++) {
            int bi = -1, bv = 0x7fffffff;
            for (int t = 0; t < nt; t++) { int v2 = s_tie[t]; if (v2 >= 0 && v2 < bv) { bv = v2; bi = t; } }
            s_out[c1 + j] = bv;
            if (bi >= 0) s_tie[bi] = -1;
        }
    }
    __syncthreads();
    float* xg = s_dyn;                 // [64][64]
    float* sWT = s_dyn + 4096;         // [c][o]
    for (int j = tid; j < 1024; j += 256) {
        int r = j >> 4, c4 = j & 15;
        float4 f = ((const float4*)(g_feaT + ((size_t)(b * N_ + s_out[r])) * CH))[c4];
        ((float4*)xg)[j] = f;
        ((float4*)sWT)[j] = ((const float4*)g_wT)[j];
    }
    __syncthreads();
    int o = tid & 63, kseg = tid >> 6;
    u64 wp[32];
#pragma unroll
    for (int c = 0; c < 32; c++) wp[c] = pk2(sWT[(2 * c) * 64 + o], sWT[(2 * c + 1) * 64 + o]);
    float mx = -3.4e38f;
    for (int k = kseg * 16; k < kseg * 16 + 16; k++) {
        const ulonglong2* xr = (const ulonglong2*)(xg + (k << 6));
        u64 acc2 = 0ull;
#pragma unroll
        for (int c4 = 0; c4 < 16; c4++) {
            ulonglong2 f = xr[c4];
            acc2 = fma2(wp[2 * c4], f.x, acc2);
            acc2 = fma2(wp[2 * c4 + 1], f.y, acc2);
        }
        float alo, ahi; upk2(acc2, alo, ahi);
        mx = fmaxf(mx, alo + ahi);
    }
    s_red[kseg * 64 + o] = mx;
    __syncthreads();
    if (tid < 64) {
        float m = fmaxf(fmaxf(s_red[tid], s_red[64 + tid]), fmaxf(s_red[128 + tid], s_red[192 + tid]));
        float val = fmaxf(fmaf(m, g_scale[tid], g_shift[tid]), 0.f);
        out[OUT1 + (b * CH + tid) * S_ + s] = val;
    }
}

// ---------- upsample ----------
__global__ __launch_bounds__(256) void k_up(const float* __restrict__ loc,
                                            const float* __restrict__ fea,
                                            float* __restrict__ out) {
    __shared__ float nx[64], ny[64], nz[64], nn[64];
    __shared__ float nf[64 * 65];
    int b = blockIdx.y, n0 = blockIdx.x * 256, tid = threadIdx.x;
    if (tid < 64) {
        float x = g_nodeloc[(b * S_ + tid) * 3 + 0];
        float y = g_nodeloc[(b * S_ + tid) * 3 + 1];
        float z = g_nodeloc[(b * S_ + tid) * 3 + 2];
        nx[tid] = x; ny[tid] = y; nz[tid] = z; nn[tid] = sq3_rn(x, y, z);
    }
    for (int j = tid; j < 64 * 64; j += 256) {
        int c = j >> 6, s2 = j & 63;
        nf[c * 65 + s2] = out[OUT1 + (b * CH + c) * S_ + s2];
    }
    __syncthreads();
    int n = n0 + tid;
    const float* lp = loc + (size_t)b * 3 * N_;
    float px = lp[n], py = lp[N_ + n], pz = lp[2 * N_ + n];
    float pn = g_xnorm[b * N_ + n];
    float d0 = 3.4e38f, d1 = 3.4e38f, d2 = 3.4e38f;
    int i0 = 0, i1 = 0, i2 = 0;
    for (int s2 = 0; s2 < 64; s2++) {
        float dot = fmaf(pz, nz[s2], fmaf(py, ny[s2], __fmul_rn(px, nx[s2])));
        float d = __fadd_rn(__fadd_rn(__fmul_rn(-2.0f, dot), pn), nn[s2]);
        if (d < d0)      { d2 = d1; i2 = i1; d1 = d0; i1 = i0; d0 = d; i0 = s2; }
        else if (d < d1) { d2 = d1; i2 = i1; d1 = d; i1 = s2; }
        else if (d < d2) { d2 = d; i2 = s2; }
    }
    float w0 = 1.0f / fmaxf(d0, 1e-10f);
    float w1 = 1.0f / fmaxf(d1, 1e-10f);
    float w2 = 1.0f / fmaxf(d2, 1e-10f);
    float ws = __fadd_rn(__fadd_rn(w0, w1), w2);
    w0 /= ws; w1 /= ws; w2 /= ws;
    const float* fb = fea + (size_t)b * CH * N_ + n;
    float* ob = out + (size_t)b * 128 * N_ + n;
#pragma unroll 8
    for (int c = 0; c < 64; c++) ob[(size_t)c * N_] = fb[(size_t)c * N_];
#pragma unroll 8
    for (int c = 0; c < 64; c++) {
        float v = fmaf(nf[c * 65 + i2], w2, fmaf(nf[c * 65 + i1], w1, __fmul_rn(nf[c * 65 + i0], w0)));
        ob[(size_t)(64 + c) * N_] = v;
    }
}

extern "C" void kernel_launch(void* const* d_in, const int* in_sizes, int n_in,
                              void* d_out, int out_size) {
    const float* fea    = (const float*)d_in[0];
    const float* loc    = (const float*)d_in[1];
    const float* w_res  = (const float*)d_in[2];
    const float* b_res  = (const float*)d_in[3];
    const float* g_res  = (const float*)d_in[4];
    const float* be_res = (const float*)d_in[5];
    const float* w_off  = (const float*)d_in[6];
    float* out = (float*)d_out;

    cudaFuncSetAttribute(k_knn, cudaFuncAttributeMaxDynamicSharedMemorySize, 65536);
    cudaFuncSetAttribute(k_moments, cudaFuncAttributeMaxDynamicSharedMemorySize, 49152);

    k_xnorm<<<(B_ * N_) / 256, 256>>>(loc);
    k_transpose<<<dim3(N_ / 32, CH / 32, B_), dim3(32, 8)>>>(fea);
    k_fps<<<B_, 1024>>>(loc);
    k_moments<<<256, 256, 49152>>>();   // 4th launch -> profiled next round
    k_ball<<<dim3(S_, B_), 128>>>(loc, w_off, out);
    k_bn<<<1, 256>>>(w_res, b_res, g_res, be_res);
    k_knn<<<dim3(S_, B_), 256, 65536>>>(loc, out);
    k_up<<<dim3(N_ / 256, B_), 256>>>(loc, fea, out);
}